// round 4
// baseline (speedup 1.0000x reference)
#include <cuda_runtime.h>
#include <cstdint>
#include <cstddef>

// ---------------------------------------------------------------------------
// MultiHeadSelfAttention: B=1024 S=64 D=1024 H=16 dk=64, rel-pos bias 15x15x16
// Round 1: tf32 mma.sync everywhere. fp32 scratch in __device__ globals.
// ---------------------------------------------------------------------------

#define M_TOT   65536      // B*S
#define DM      1024
#define NHEAD   16
#define DK      64
#define SEQ     64

__device__ float g_q[(size_t)M_TOT * DM];
__device__ float g_k[(size_t)M_TOT * DM];
__device__ float g_v[(size_t)M_TOT * DM];
__device__ float g_ctx[(size_t)M_TOT * DM];

// ---------------- PTX helpers ----------------
__device__ __forceinline__ uint32_t f2tf(float x) {
    uint32_t r;
    asm("cvt.rna.tf32.f32 %0, %1;" : "=r"(r) : "f"(x));
    return r;
}

__device__ __forceinline__ void mma_tf32(float* d, const uint32_t* a, const uint32_t* b) {
    asm volatile(
        "mma.sync.aligned.m16n8k8.row.col.f32.tf32.tf32.f32 "
        "{%0,%1,%2,%3}, {%4,%5,%6,%7}, {%8,%9}, {%0,%1,%2,%3};"
        : "+f"(d[0]), "+f"(d[1]), "+f"(d[2]), "+f"(d[3])
        : "r"(a[0]), "r"(a[1]), "r"(a[2]), "r"(a[3]), "r"(b[0]), "r"(b[1]));
}

__device__ __forceinline__ void cp16(uint32_t s, const float* g) {
    asm volatile("cp.async.ca.shared.global [%0], [%1], 16;" :: "r"(s), "l"(g));
}
__device__ __forceinline__ void cp_commit() { asm volatile("cp.async.commit_group;"); }
__device__ __forceinline__ void cp_wait0()  { asm volatile("cp.async.wait_group 0;"); }

// ---------------- GEMM body: C[128x128 tile] = A[.,1024] @ W[1024,.] + bias --
// BM=128, BN=128, BK=16. 256 threads = 8 warps (2 m x 4 n), warp tile 64x32.
// smem strides padded for conflict-free tf32 fragment loads:
//   A stride 20  -> bank = (g*20+k)%32 = (4g+k)%32 distinct
//   B stride 136 -> bank = (k*136+n)%32 = (8k+n)%32 distinct
#define GA_ST 20
#define GB_ST 136

__device__ __forceinline__ void gemm_body(
    const float* __restrict__ A, const float* __restrict__ W,
    const float* __restrict__ bias, float* __restrict__ C,
    int bn, int bm)
{
    __shared__ __align__(16) float sA[2][128 * GA_ST];
    __shared__ __align__(16) float sB[2][16 * GB_ST];

    const int tid  = threadIdx.x;
    const int lane = tid & 31;
    const int warp = tid >> 5;
    const int wm = warp >> 2;      // 0..1
    const int wn = warp & 3;       // 0..3
    const int g  = lane >> 2;      // 0..7
    const int t  = lane & 3;       // 0..3

    const float* Ab = A + (size_t)bm * 128 * DM;
    const float* Wb = W + bn * 128;

    float acc[4][4][4];
#pragma unroll
    for (int i = 0; i < 4; i++)
#pragma unroll
        for (int j = 0; j < 4; j++)
#pragma unroll
            for (int r = 0; r < 4; r++) acc[i][j][r] = 0.f;

    // per-chunk cooperative load: A 128x16 floats, B 16x128 floats (16B chunks)
    auto load_chunk = [&](int kc, int buf) {
#pragma unroll
        for (int c = 0; c < 2; c++) {
            int id = tid + c * 256;
            int ar = id >> 2, ac = (id & 3) * 4;
            cp16((uint32_t)__cvta_generic_to_shared(&sA[buf][ar * GA_ST + ac]),
                 Ab + (size_t)ar * DM + kc * 16 + ac);
            int br = id >> 5, bc = (id & 31) * 4;
            cp16((uint32_t)__cvta_generic_to_shared(&sB[buf][br * GB_ST + bc]),
                 Wb + (size_t)(kc * 16 + br) * DM + bc);
        }
        cp_commit();
    };

    load_chunk(0, 0);
    for (int kc = 0; kc < 64; kc++) {
        cp_wait0();
        __syncthreads();
        if (kc < 63) load_chunk(kc + 1, (kc + 1) & 1);
        const float* cA = sA[kc & 1];
        const float* cB = sB[kc & 1];
#pragma unroll
        for (int ks = 0; ks < 2; ks++) {
            uint32_t af[4][4];
#pragma unroll
            for (int mt = 0; mt < 4; mt++) {
                int r0 = wm * 64 + mt * 16 + g;
                int c0 = ks * 8 + t;
                af[mt][0] = f2tf(cA[r0 * GA_ST + c0]);
                af[mt][1] = f2tf(cA[(r0 + 8) * GA_ST + c0]);
                af[mt][2] = f2tf(cA[r0 * GA_ST + c0 + 4]);
                af[mt][3] = f2tf(cA[(r0 + 8) * GA_ST + c0 + 4]);
            }
            uint32_t bf[4][2];
#pragma unroll
            for (int nt = 0; nt < 4; nt++) {
                int n0 = wn * 32 + nt * 8 + g;
                int k0 = ks * 8 + t;
                bf[nt][0] = f2tf(cB[k0 * GB_ST + n0]);
                bf[nt][1] = f2tf(cB[(k0 + 4) * GB_ST + n0]);
            }
#pragma unroll
            for (int mt = 0; mt < 4; mt++)
#pragma unroll
                for (int nt = 0; nt < 4; nt++)
                    mma_tf32(acc[mt][nt], af[mt], bf[nt]);
        }
        __syncthreads();
    }

    // epilogue: + bias, fp32 store
#pragma unroll
    for (int mt = 0; mt < 4; mt++) {
        int r0 = bm * 128 + wm * 64 + mt * 16 + g;
#pragma unroll
        for (int nt = 0; nt < 4; nt++) {
            int c0 = bn * 128 + wn * 32 + nt * 8 + t * 2;
            float b0 = bias[c0], b1 = bias[c0 + 1];
            C[(size_t)r0 * DM + c0]           = acc[mt][nt][0] + b0;
            C[(size_t)r0 * DM + c0 + 1]       = acc[mt][nt][1] + b1;
            C[(size_t)(r0 + 8) * DM + c0]     = acc[mt][nt][2] + b0;
            C[(size_t)(r0 + 8) * DM + c0 + 1] = acc[mt][nt][3] + b1;
        }
    }
}

// Fused QKV: grid (24, 512); blockIdx.x/8 selects which projection.
__global__ __launch_bounds__(256) void qkv_gemm(
    const float* __restrict__ X,
    const float* __restrict__ Wq, const float* __restrict__ Wk, const float* __restrict__ Wv,
    const float* __restrict__ bq, const float* __restrict__ bk, const float* __restrict__ bv)
{
    int which = blockIdx.x >> 3;
    int bn = blockIdx.x & 7;
    const float* W = (which == 0) ? Wq : (which == 1) ? Wk : Wv;
    const float* b = (which == 0) ? bq : (which == 1) ? bk : bv;
    float* C = (which == 0) ? g_q : (which == 1) ? g_k : g_v;
    gemm_body(X, W, b, C, bn, blockIdx.y);
}

__global__ __launch_bounds__(256) void out_gemm(
    const float* __restrict__ Wo, const float* __restrict__ bo, float* __restrict__ out)
{
    gemm_body(g_ctx, Wo, bo, out, blockIdx.x, blockIdx.y);
}

// ---------------- Attention kernel: one CTA per (b,h) ----------------
// smem: sQ holds Q then scores/P (stride 68, conflict-free frag loads),
//       sK holds K then V^T. 35.7 KB static -> high occupancy.
__device__ __forceinline__ float bias_at(int i, int j, const float* sBias) {
    int dr = (i >> 3) - (j >> 3) + 7;   // |diff|<=7 on 8x8 board, clip is no-op
    int df = (i & 7) - (j & 7) + 7;
    return sBias[dr * 15 + df];
}

__global__ __launch_bounds__(128) void attn_kernel(const float* __restrict__ bias_table)
{
    __shared__ __align__(16) float sQ[64 * 68];
    __shared__ __align__(16) float sK[64 * 68];
    __shared__ float sBias[232];

    const int tid  = threadIdx.x;
    const int lane = tid & 31;
    const int warp = tid >> 5;
    const int g = lane >> 2, t = lane & 3;
    const int bh = blockIdx.x;
    const int b = bh >> 4, h = bh & 15;

    const float* qb = g_q + (size_t)b * SEQ * DM + h * DK;
    const float* kb = g_k + (size_t)b * SEQ * DM + h * DK;
    const float* vb = g_v + (size_t)b * SEQ * DM + h * DK;

    // load Q, K (64x64 each, coalesced float4)
    for (int i = tid; i < 1024; i += 128) {
        int s = i >> 4, d4 = (i & 15) * 4;
        float4 qv = *(const float4*)(qb + (size_t)s * DM + d4);
        float4 kv = *(const float4*)(kb + (size_t)s * DM + d4);
        *(float4*)&sQ[s * 68 + d4] = qv;
        *(float4*)&sK[s * 68 + d4] = kv;
    }
    for (int i = tid; i < 225; i += 128) sBias[i] = bias_table[i * 16 + h];
    __syncthreads();

    // scores = Q @ K^T : warp computes rows [warp*16, warp*16+16), all 64 cols
    float acc[8][4];
#pragma unroll
    for (int nt = 0; nt < 8; nt++)
#pragma unroll
        for (int r = 0; r < 4; r++) acc[nt][r] = 0.f;

#pragma unroll
    for (int ks = 0; ks < 8; ks++) {
        uint32_t af[4];
        int r0 = warp * 16 + g;
        int c0 = ks * 8 + t;
        af[0] = f2tf(sQ[r0 * 68 + c0]);
        af[1] = f2tf(sQ[(r0 + 8) * 68 + c0]);
        af[2] = f2tf(sQ[r0 * 68 + c0 + 4]);
        af[3] = f2tf(sQ[(r0 + 8) * 68 + c0 + 4]);
#pragma unroll
        for (int nt = 0; nt < 8; nt++) {
            uint32_t bf[2];
            int j0 = nt * 8 + g;
            bf[0] = f2tf(sK[j0 * 68 + c0]);
            bf[1] = f2tf(sK[j0 * 68 + c0 + 4]);
            mma_tf32(acc[nt], af, bf);
        }
    }
    __syncthreads();   // all warps done reading sQ (Q) and sK (K)

    // scale + bias, write scores into sQ; simultaneously load V^T into sK
    const float scale = 0.125f;  // 1/sqrt(64)
#pragma unroll
    for (int nt = 0; nt < 8; nt++) {
        int i0 = warp * 16 + g;
        int j0 = nt * 8 + t * 2;
        sQ[i0 * 68 + j0]           = acc[nt][0] * scale + bias_at(i0, j0, sBias);
        sQ[i0 * 68 + j0 + 1]       = acc[nt][1] * scale + bias_at(i0, j0 + 1, sBias);
        sQ[(i0 + 8) * 68 + j0]     = acc[nt][2] * scale + bias_at(i0 + 8, j0, sBias);
        sQ[(i0 + 8) * 68 + j0 + 1] = acc[nt][3] * scale + bias_at(i0 + 8, j0 + 1, sBias);
    }
    for (int i = tid; i < 1024; i += 128) {
        int s = i >> 4, d4 = (i & 15) * 4;
        float4 vv = *(const float4*)(vb + (size_t)s * DM + d4);
        sK[(d4 + 0) * 68 + s] = vv.x;    // V^T: [d][s]
        sK[(d4 + 1) * 68 + s] = vv.y;
        sK[(d4 + 2) * 68 + s] = vv.z;
        sK[(d4 + 3) * 68 + s] = vv.w;
    }
    __syncthreads();

    // softmax: 2 threads per row, 32 cols each
    {
        int row = tid >> 1;
        float* sr = sQ + row * 68 + (tid & 1) * 32;
        float m = -1e30f;
#pragma unroll
        for (int c = 0; c < 32; c++) m = fmaxf(m, sr[c]);
        m = fmaxf(m, __shfl_xor_sync(0xffffffffu, m, 1));
        float ssum = 0.f;
#pragma unroll
        for (int c = 0; c < 32; c++) { float e = __expf(sr[c] - m); sr[c] = e; ssum += e; }
        ssum += __shfl_xor_sync(0xffffffffu, ssum, 1);
        float inv = 1.f / ssum;
#pragma unroll
        for (int c = 0; c < 32; c++) sr[c] *= inv;
    }
    __syncthreads();

    // ctx = P @ V : P in sQ (stride 68), V^T in sK ([d][s], stride 68)
    float o[8][4];
#pragma unroll
    for (int nt = 0; nt < 8; nt++)
#pragma unroll
        for (int r = 0; r < 4; r++) o[nt][r] = 0.f;

#pragma unroll
    for (int ks = 0; ks < 8; ks++) {
        uint32_t af[4];
        int r0 = warp * 16 + g;
        int c0 = ks * 8 + t;            // k index = key position s
        af[0] = f2tf(sQ[r0 * 68 + c0]);
        af[1] = f2tf(sQ[(r0 + 8) * 68 + c0]);
        af[2] = f2tf(sQ[r0 * 68 + c0 + 4]);
        af[3] = f2tf(sQ[(r0 + 8) * 68 + c0 + 4]);
#pragma unroll
        for (int nt = 0; nt < 8; nt++) {
            uint32_t bf[2];
            int d0 = nt * 8 + g;        // n index = head dim d
            bf[0] = f2tf(sK[d0 * 68 + c0]);
            bf[1] = f2tf(sK[d0 * 68 + c0 + 4]);
            mma_tf32(o[nt], af, bf);
        }
    }

    float* cb = g_ctx + (size_t)b * SEQ * DM + h * DK;
#pragma unroll
    for (int nt = 0; nt < 8; nt++) {
        int i0 = warp * 16 + g;
        int d0 = nt * 8 + t * 2;
        cb[(size_t)i0 * DM + d0]           = o[nt][0];
        cb[(size_t)i0 * DM + d0 + 1]       = o[nt][1];
        cb[(size_t)(i0 + 8) * DM + d0]     = o[nt][2];
        cb[(size_t)(i0 + 8) * DM + d0 + 1] = o[nt][3];
    }
}

// ---------------- launch ----------------
extern "C" void kernel_launch(void* const* d_in, const int* in_sizes, int n_in,
                              void* d_out, int out_size)
{
    const float* x  = (const float*)d_in[0];
    const float* Wq = (const float*)d_in[1];
    const float* bq = (const float*)d_in[2];
    const float* Wk = (const float*)d_in[3];
    const float* bk = (const float*)d_in[4];
    const float* Wv = (const float*)d_in[5];
    const float* bv = (const float*)d_in[6];
    const float* Wo = (const float*)d_in[7];
    const float* bo = (const float*)d_in[8];
    const float* bt = (const float*)d_in[9];
    float* out = (float*)d_out;

    qkv_gemm<<<dim3(24, 512), 256>>>(x, Wq, Wk, Wv, bq, bk, bv);
    attn_kernel<<<16384, 128>>>(bt);
    out_gemm<<<dim3(8, 512), 256>>>(Wo, bo, out);
}

// round 5
// speedup vs baseline: 1.0024x; 1.0024x over previous
#include <cuda_runtime.h>
#include <cstdint>
#include <cstddef>

// ---------------------------------------------------------------------------
// MultiHeadSelfAttention: B=1024 S=64 D=1024 H=16 dk=64, rel-pos bias 15x15x16
// Round 1: tf32 mma.sync everywhere. fp32 scratch in __device__ globals.
// ---------------------------------------------------------------------------

#define M_TOT   65536      // B*S
#define DM      1024
#define NHEAD   16
#define DK      64
#define SEQ     64

__device__ float g_q[(size_t)M_TOT * DM];
__device__ float g_k[(size_t)M_TOT * DM];
__device__ float g_v[(size_t)M_TOT * DM];
__device__ float g_ctx[(size_t)M_TOT * DM];

// ---------------- PTX helpers ----------------
__device__ __forceinline__ uint32_t f2tf(float x) {
    uint32_t r;
    asm("cvt.rna.tf32.f32 %0, %1;" : "=r"(r) : "f"(x));
    return r;
}

__device__ __forceinline__ void mma_tf32(float* d, const uint32_t* a, const uint32_t* b) {
    asm volatile(
        "mma.sync.aligned.m16n8k8.row.col.f32.tf32.tf32.f32 "
        "{%0,%1,%2,%3}, {%4,%5,%6,%7}, {%8,%9}, {%0,%1,%2,%3};"
        : "+f"(d[0]), "+f"(d[1]), "+f"(d[2]), "+f"(d[3])
        : "r"(a[0]), "r"(a[1]), "r"(a[2]), "r"(a[3]), "r"(b[0]), "r"(b[1]));
}

__device__ __forceinline__ void cp16(uint32_t s, const float* g) {
    asm volatile("cp.async.ca.shared.global [%0], [%1], 16;" :: "r"(s), "l"(g));
}
__device__ __forceinline__ void cp_commit() { asm volatile("cp.async.commit_group;"); }
__device__ __forceinline__ void cp_wait0()  { asm volatile("cp.async.wait_group 0;"); }

// ---------------- GEMM body: C[128x128 tile] = A[.,1024] @ W[1024,.] + bias --
// BM=128, BN=128, BK=16. 256 threads = 8 warps (2 m x 4 n), warp tile 64x32.
// smem strides padded for conflict-free tf32 fragment loads:
//   A stride 20  -> bank = (g*20+k)%32 = (4g+k)%32 distinct
//   B stride 136 -> bank = (k*136+n)%32 = (8k+n)%32 distinct
#define GA_ST 20
#define GB_ST 136

__device__ __forceinline__ void gemm_body(
    const float* __restrict__ A, const float* __restrict__ W,
    const float* __restrict__ bias, float* __restrict__ C,
    int bn, int bm)
{
    __shared__ __align__(16) float sA[2][128 * GA_ST];
    __shared__ __align__(16) float sB[2][16 * GB_ST];

    const int tid  = threadIdx.x;
    const int lane = tid & 31;
    const int warp = tid >> 5;
    const int wm = warp >> 2;      // 0..1
    const int wn = warp & 3;       // 0..3
    const int g  = lane >> 2;      // 0..7
    const int t  = lane & 3;       // 0..3

    const float* Ab = A + (size_t)bm * 128 * DM;
    const float* Wb = W + bn * 128;

    float acc[4][4][4];
#pragma unroll
    for (int i = 0; i < 4; i++)
#pragma unroll
        for (int j = 0; j < 4; j++)
#pragma unroll
            for (int r = 0; r < 4; r++) acc[i][j][r] = 0.f;

    // per-chunk cooperative load: A 128x16 floats, B 16x128 floats (16B chunks)
    auto load_chunk = [&](int kc, int buf) {
#pragma unroll
        for (int c = 0; c < 2; c++) {
            int id = tid + c * 256;
            int ar = id >> 2, ac = (id & 3) * 4;
            cp16((uint32_t)__cvta_generic_to_shared(&sA[buf][ar * GA_ST + ac]),
                 Ab + (size_t)ar * DM + kc * 16 + ac);
            int br = id >> 5, bc = (id & 31) * 4;
            cp16((uint32_t)__cvta_generic_to_shared(&sB[buf][br * GB_ST + bc]),
                 Wb + (size_t)(kc * 16 + br) * DM + bc);
        }
        cp_commit();
    };

    load_chunk(0, 0);
    for (int kc = 0; kc < 64; kc++) {
        cp_wait0();
        __syncthreads();
        if (kc < 63) load_chunk(kc + 1, (kc + 1) & 1);
        const float* cA = sA[kc & 1];
        const float* cB = sB[kc & 1];
#pragma unroll
        for (int ks = 0; ks < 2; ks++) {
            uint32_t af[4][4];
#pragma unroll
            for (int mt = 0; mt < 4; mt++) {
                int r0 = wm * 64 + mt * 16 + g;
                int c0 = ks * 8 + t;
                af[mt][0] = f2tf(cA[r0 * GA_ST + c0]);
                af[mt][1] = f2tf(cA[(r0 + 8) * GA_ST + c0]);
                af[mt][2] = f2tf(cA[r0 * GA_ST + c0 + 4]);
                af[mt][3] = f2tf(cA[(r0 + 8) * GA_ST + c0 + 4]);
            }
            uint32_t bf[4][2];
#pragma unroll
            for (int nt = 0; nt < 4; nt++) {
                int n0 = wn * 32 + nt * 8 + g;
                int k0 = ks * 8 + t;
                bf[nt][0] = f2tf(cB[k0 * GB_ST + n0]);
                bf[nt][1] = f2tf(cB[(k0 + 4) * GB_ST + n0]);
            }
#pragma unroll
            for (int mt = 0; mt < 4; mt++)
#pragma unroll
                for (int nt = 0; nt < 4; nt++)
                    mma_tf32(acc[mt][nt], af[mt], bf[nt]);
        }
        __syncthreads();
    }

    // epilogue: + bias, fp32 store
#pragma unroll
    for (int mt = 0; mt < 4; mt++) {
        int r0 = bm * 128 + wm * 64 + mt * 16 + g;
#pragma unroll
        for (int nt = 0; nt < 4; nt++) {
            int c0 = bn * 128 + wn * 32 + nt * 8 + t * 2;
            float b0 = bias[c0], b1 = bias[c0 + 1];
            C[(size_t)r0 * DM + c0]           = acc[mt][nt][0] + b0;
            C[(size_t)r0 * DM + c0 + 1]       = acc[mt][nt][1] + b1;
            C[(size_t)(r0 + 8) * DM + c0]     = acc[mt][nt][2] + b0;
            C[(size_t)(r0 + 8) * DM + c0 + 1] = acc[mt][nt][3] + b1;
        }
    }
}

// Fused QKV: grid (24, 512); blockIdx.x/8 selects which projection.
__global__ __launch_bounds__(256) void qkv_gemm(
    const float* __restrict__ X,
    const float* __restrict__ Wq, const float* __restrict__ Wk, const float* __restrict__ Wv,
    const float* __restrict__ bq, const float* __restrict__ bk, const float* __restrict__ bv)
{
    int which = blockIdx.x >> 3;
    int bn = blockIdx.x & 7;
    const float* W = (which == 0) ? Wq : (which == 1) ? Wk : Wv;
    const float* b = (which == 0) ? bq : (which == 1) ? bk : bv;
    float* C = (which == 0) ? g_q : (which == 1) ? g_k : g_v;
    gemm_body(X, W, b, C, bn, blockIdx.y);
}

__global__ __launch_bounds__(256) void out_gemm(
    const float* __restrict__ Wo, const float* __restrict__ bo, float* __restrict__ out)
{
    gemm_body(g_ctx, Wo, bo, out, blockIdx.x, blockIdx.y);
}

// ---------------- Attention kernel: one CTA per (b,h) ----------------
// smem: sQ holds Q then scores/P (stride 68, conflict-free frag loads),
//       sK holds K then V^T. 35.7 KB static -> high occupancy.
__device__ __forceinline__ float bias_at(int i, int j, const float* sBias) {
    int dr = (i >> 3) - (j >> 3) + 7;   // |diff|<=7 on 8x8 board, clip is no-op
    int df = (i & 7) - (j & 7) + 7;
    return sBias[dr * 15 + df];
}

__global__ __launch_bounds__(128) void attn_kernel(const float* __restrict__ bias_table)
{
    __shared__ __align__(16) float sQ[64 * 68];
    __shared__ __align__(16) float sK[64 * 68];
    __shared__ float sBias[232];

    const int tid  = threadIdx.x;
    const int lane = tid & 31;
    const int warp = tid >> 5;
    const int g = lane >> 2, t = lane & 3;
    const int bh = blockIdx.x;
    const int b = bh >> 4, h = bh & 15;

    const float* qb = g_q + (size_t)b * SEQ * DM + h * DK;
    const float* kb = g_k + (size_t)b * SEQ * DM + h * DK;
    const float* vb = g_v + (size_t)b * SEQ * DM + h * DK;

    // load Q, K (64x64 each, coalesced float4)
    for (int i = tid; i < 1024; i += 128) {
        int s = i >> 4, d4 = (i & 15) * 4;
        float4 qv = *(const float4*)(qb + (size_t)s * DM + d4);
        float4 kv = *(const float4*)(kb + (size_t)s * DM + d4);
        *(float4*)&sQ[s * 68 + d4] = qv;
        *(float4*)&sK[s * 68 + d4] = kv;
    }
    for (int i = tid; i < 225; i += 128) sBias[i] = bias_table[i * 16 + h];
    __syncthreads();

    // scores = Q @ K^T : warp computes rows [warp*16, warp*16+16), all 64 cols
    float acc[8][4];
#pragma unroll
    for (int nt = 0; nt < 8; nt++)
#pragma unroll
        for (int r = 0; r < 4; r++) acc[nt][r] = 0.f;

#pragma unroll
    for (int ks = 0; ks < 8; ks++) {
        uint32_t af[4];
        int r0 = warp * 16 + g;
        int c0 = ks * 8 + t;
        af[0] = f2tf(sQ[r0 * 68 + c0]);
        af[1] = f2tf(sQ[(r0 + 8) * 68 + c0]);
        af[2] = f2tf(sQ[r0 * 68 + c0 + 4]);
        af[3] = f2tf(sQ[(r0 + 8) * 68 + c0 + 4]);
#pragma unroll
        for (int nt = 0; nt < 8; nt++) {
            uint32_t bf[2];
            int j0 = nt * 8 + g;
            bf[0] = f2tf(sK[j0 * 68 + c0]);
            bf[1] = f2tf(sK[j0 * 68 + c0 + 4]);
            mma_tf32(acc[nt], af, bf);
        }
    }
    __syncthreads();   // all warps done reading sQ (Q) and sK (K)

    // scale + bias, write scores into sQ; simultaneously load V^T into sK
    const float scale = 0.125f;  // 1/sqrt(64)
#pragma unroll
    for (int nt = 0; nt < 8; nt++) {
        int i0 = warp * 16 + g;
        int j0 = nt * 8 + t * 2;
        sQ[i0 * 68 + j0]           = acc[nt][0] * scale + bias_at(i0, j0, sBias);
        sQ[i0 * 68 + j0 + 1]       = acc[nt][1] * scale + bias_at(i0, j0 + 1, sBias);
        sQ[(i0 + 8) * 68 + j0]     = acc[nt][2] * scale + bias_at(i0 + 8, j0, sBias);
        sQ[(i0 + 8) * 68 + j0 + 1] = acc[nt][3] * scale + bias_at(i0 + 8, j0 + 1, sBias);
    }
    for (int i = tid; i < 1024; i += 128) {
        int s = i >> 4, d4 = (i & 15) * 4;
        float4 vv = *(const float4*)(vb + (size_t)s * DM + d4);
        sK[(d4 + 0) * 68 + s] = vv.x;    // V^T: [d][s]
        sK[(d4 + 1) * 68 + s] = vv.y;
        sK[(d4 + 2) * 68 + s] = vv.z;
        sK[(d4 + 3) * 68 + s] = vv.w;
    }
    __syncthreads();

    // softmax: 2 threads per row, 32 cols each
    {
        int row = tid >> 1;
        float* sr = sQ + row * 68 + (tid & 1) * 32;
        float m = -1e30f;
#pragma unroll
        for (int c = 0; c < 32; c++) m = fmaxf(m, sr[c]);
        m = fmaxf(m, __shfl_xor_sync(0xffffffffu, m, 1));
        float ssum = 0.f;
#pragma unroll
        for (int c = 0; c < 32; c++) { float e = __expf(sr[c] - m); sr[c] = e; ssum += e; }
        ssum += __shfl_xor_sync(0xffffffffu, ssum, 1);
        float inv = 1.f / ssum;
#pragma unroll
        for (int c = 0; c < 32; c++) sr[c] *= inv;
    }
    __syncthreads();

    // ctx = P @ V : P in sQ (stride 68), V^T in sK ([d][s], stride 68)
    float o[8][4];
#pragma unroll
    for (int nt = 0; nt < 8; nt++)
#pragma unroll
        for (int r = 0; r < 4; r++) o[nt][r] = 0.f;

#pragma unroll
    for (int ks = 0; ks < 8; ks++) {
        uint32_t af[4];
        int r0 = warp * 16 + g;
        int c0 = ks * 8 + t;            // k index = key position s
        af[0] = f2tf(sQ[r0 * 68 + c0]);
        af[1] = f2tf(sQ[(r0 + 8) * 68 + c0]);
        af[2] = f2tf(sQ[r0 * 68 + c0 + 4]);
        af[3] = f2tf(sQ[(r0 + 8) * 68 + c0 + 4]);
#pragma unroll
        for (int nt = 0; nt < 8; nt++) {
            uint32_t bf[2];
            int d0 = nt * 8 + g;        // n index = head dim d
            bf[0] = f2tf(sK[d0 * 68 + c0]);
            bf[1] = f2tf(sK[d0 * 68 + c0 + 4]);
            mma_tf32(o[nt], af, bf);
        }
    }

    float* cb = g_ctx + (size_t)b * SEQ * DM + h * DK;
#pragma unroll
    for (int nt = 0; nt < 8; nt++) {
        int i0 = warp * 16 + g;
        int d0 = nt * 8 + t * 2;
        cb[(size_t)i0 * DM + d0]           = o[nt][0];
        cb[(size_t)i0 * DM + d0 + 1]       = o[nt][1];
        cb[(size_t)(i0 + 8) * DM + d0]     = o[nt][2];
        cb[(size_t)(i0 + 8) * DM + d0 + 1] = o[nt][3];
    }
}

// ---------------- launch ----------------
extern "C" void kernel_launch(void* const* d_in, const int* in_sizes, int n_in,
                              void* d_out, int out_size)
{
    const float* x  = (const float*)d_in[0];
    const float* Wq = (const float*)d_in[1];
    const float* bq = (const float*)d_in[2];
    const float* Wk = (const float*)d_in[3];
    const float* bk = (const float*)d_in[4];
    const float* Wv = (const float*)d_in[5];
    const float* bv = (const float*)d_in[6];
    const float* Wo = (const float*)d_in[7];
    const float* bo = (const float*)d_in[8];
    const float* bt = (const float*)d_in[9];
    float* out = (float*)d_out;

    qkv_gemm<<<dim3(24, 512), 256>>>(x, Wq, Wk, Wv, bq, bk, bv);
    attn_kernel<<<16384, 128>>>(bt);
    out_gemm<<<dim3(8, 512), 256>>>(Wo, bo, out);
}

// round 7
// speedup vs baseline: 1.0718x; 1.0692x over previous
#include <cuda_runtime.h>
#include <cstdint>
#include <cstddef>

// ---------------------------------------------------------------------------
// MHSA B=1024 S=64 D=1024 H=16 dk=64.
// R7: legacy tf32 mma.sync (tcgen05 PTX rejected by this toolchain: target
// sm_103 without 'a'). All tf32 rounding hoisted to producers -> zero CVT in
// GEMM/attn inner loops. Numerically identical rounding points to R1.
// ---------------------------------------------------------------------------

#define M_TOT   65536      // B*S
#define DM      1024
#define SEQ     64
#define DK      64

__device__ float g_q[(size_t)M_TOT * DM];
__device__ float g_k[(size_t)M_TOT * DM];
__device__ float g_v[(size_t)M_TOT * DM];
__device__ float g_ctx[(size_t)M_TOT * DM];
__device__ float g_xr[(size_t)M_TOT * DM];        // tf32-rounded X
__device__ float g_w[(size_t)4 * DM * DM];        // tf32-rounded Wq,Wk,Wv,Wo

// ---------------- PTX helpers ----------------
__device__ __forceinline__ uint32_t f2tf(float x) {
    uint32_t r;
    asm("cvt.rna.tf32.f32 %0, %1;" : "=r"(r) : "f"(x));
    return r;
}
__device__ __forceinline__ float rnd(float x) { return __uint_as_float(f2tf(x)); }

__device__ __forceinline__ void mma_tf32(float* d, const uint32_t* a, const uint32_t* b) {
    asm volatile(
        "mma.sync.aligned.m16n8k8.row.col.f32.tf32.tf32.f32 "
        "{%0,%1,%2,%3}, {%4,%5,%6,%7}, {%8,%9}, {%0,%1,%2,%3};"
        : "+f"(d[0]), "+f"(d[1]), "+f"(d[2]), "+f"(d[3])
        : "r"(a[0]), "r"(a[1]), "r"(a[2]), "r"(a[3]), "r"(b[0]), "r"(b[1]));
}

__device__ __forceinline__ void cp16(uint32_t s, const float* g) {
    asm volatile("cp.async.ca.shared.global [%0], [%1], 16;" :: "r"(s), "l"(g));
}
__device__ __forceinline__ void cp_commit() { asm volatile("cp.async.commit_group;"); }
__device__ __forceinline__ void cp_wait0()  { asm volatile("cp.async.wait_group 0;"); }

// ---------------- prepasses: hoist tf32 rounding ----------------
__global__ __launch_bounds__(256) void round_x(const float* __restrict__ x) {
    const float4* src = (const float4*)x;
    float4* dst = (float4*)g_xr;
#pragma unroll
    for (int j = 0; j < 4; j++) {
        size_t i = (size_t)blockIdx.x * 1024 + j * 256 + threadIdx.x;
        float4 v = src[i];
        v.x = rnd(v.x); v.y = rnd(v.y); v.z = rnd(v.z); v.w = rnd(v.w);
        dst[i] = v;
    }
}

__global__ __launch_bounds__(256) void round_w(
    const float* __restrict__ Wq, const float* __restrict__ Wk,
    const float* __restrict__ Wv, const float* __restrict__ Wo)
{
    size_t id = (size_t)blockIdx.x * 256 + threadIdx.x;   // float4 index, 1M total
    int mat = (int)(id >> 18);                            // 256K float4 per matrix
    size_t off = id & 0x3FFFF;
    const float4* src = (const float4*)((mat == 0) ? Wq : (mat == 1) ? Wk :
                                        (mat == 2) ? Wv : Wo);
    float4 v = src[off];
    v.x = rnd(v.x); v.y = rnd(v.y); v.z = rnd(v.z); v.w = rnd(v.w);
    ((float4*)g_w)[id] = v;
}

// ---------------- GEMM body: C[128x128 tile] = A[.,1024] @ W[1024,.] + bias --
// BM=128, BN=128, BK=16. 256 threads = 8 warps (2m x 4n), warp tile 64x32.
// A and W are pre-rounded tf32 bits -> fragment loads are plain LDS, no CVT.
#define GA_ST 20
#define GB_ST 136

template <bool RND_OUT>
__device__ __forceinline__ void gemm_body(
    const float* __restrict__ A, const float* __restrict__ W,
    const float* __restrict__ bias, float* __restrict__ C,
    int bn, int bm)
{
    __shared__ __align__(16) float sA[2][128 * GA_ST];
    __shared__ __align__(16) float sB[2][16 * GB_ST];

    const int tid  = threadIdx.x;
    const int lane = tid & 31;
    const int warp = tid >> 5;
    const int wm = warp >> 2;
    const int wn = warp & 3;
    const int g  = lane >> 2;
    const int t  = lane & 3;

    const float* Ab = A + (size_t)bm * 128 * DM;
    const float* Wb = W + bn * 128;

    float acc[4][4][4];
#pragma unroll
    for (int i = 0; i < 4; i++)
#pragma unroll
        for (int j = 0; j < 4; j++)
#pragma unroll
            for (int r = 0; r < 4; r++) acc[i][j][r] = 0.f;

    auto load_chunk = [&](int kc, int buf) {
#pragma unroll
        for (int c = 0; c < 2; c++) {
            int id = tid + c * 256;
            int ar = id >> 2, ac = (id & 3) * 4;
            cp16((uint32_t)__cvta_generic_to_shared(&sA[buf][ar * GA_ST + ac]),
                 Ab + (size_t)ar * DM + kc * 16 + ac);
            int br = id >> 5, bc = (id & 31) * 4;
            cp16((uint32_t)__cvta_generic_to_shared(&sB[buf][br * GB_ST + bc]),
                 Wb + (size_t)(kc * 16 + br) * DM + bc);
        }
        cp_commit();
    };

    load_chunk(0, 0);
#pragma unroll 2
    for (int kc = 0; kc < 64; kc++) {
        cp_wait0();
        __syncthreads();
        if (kc < 63) load_chunk(kc + 1, (kc + 1) & 1);
        const uint32_t* cA = (const uint32_t*)sA[kc & 1];
        const uint32_t* cB = (const uint32_t*)sB[kc & 1];
#pragma unroll
        for (int ks = 0; ks < 2; ks++) {
            uint32_t af[4][4];
#pragma unroll
            for (int mt = 0; mt < 4; mt++) {
                int r0 = wm * 64 + mt * 16 + g;
                int c0 = ks * 8 + t;
                af[mt][0] = cA[r0 * GA_ST + c0];
                af[mt][1] = cA[(r0 + 8) * GA_ST + c0];
                af[mt][2] = cA[r0 * GA_ST + c0 + 4];
                af[mt][3] = cA[(r0 + 8) * GA_ST + c0 + 4];
            }
            uint32_t bf[4][2];
#pragma unroll
            for (int nt = 0; nt < 4; nt++) {
                int n0 = wn * 32 + nt * 8 + g;
                int k0 = ks * 8 + t;
                bf[nt][0] = cB[k0 * GB_ST + n0];
                bf[nt][1] = cB[(k0 + 4) * GB_ST + n0];
            }
#pragma unroll
            for (int mt = 0; mt < 4; mt++)
#pragma unroll
                for (int nt = 0; nt < 4; nt++)
                    mma_tf32(acc[mt][nt], af[mt], bf[nt]);
        }
        __syncthreads();
    }

#pragma unroll
    for (int mt = 0; mt < 4; mt++) {
        int r0 = bm * 128 + wm * 64 + mt * 16 + g;
#pragma unroll
        for (int nt = 0; nt < 4; nt++) {
            int c0 = bn * 128 + wn * 32 + nt * 8 + t * 2;
            float b0 = bias[c0], b1 = bias[c0 + 1];
            float v0 = acc[mt][nt][0] + b0;
            float v1 = acc[mt][nt][1] + b1;
            float v2 = acc[mt][nt][2] + b0;
            float v3 = acc[mt][nt][3] + b1;
            if (RND_OUT) { v0 = rnd(v0); v1 = rnd(v1); v2 = rnd(v2); v3 = rnd(v3); }
            C[(size_t)r0 * DM + c0]           = v0;
            C[(size_t)r0 * DM + c0 + 1]       = v1;
            C[(size_t)(r0 + 8) * DM + c0]     = v2;
            C[(size_t)(r0 + 8) * DM + c0 + 1] = v3;
        }
    }
}

// Fused QKV: grid (24, 512). Outputs are tf32-rounded (post-bias) so the
// attention kernel needs no CVT on Q/K/V.
__global__ __launch_bounds__(256) void qkv_gemm(
    const float* __restrict__ bq, const float* __restrict__ bk, const float* __restrict__ bv)
{
    int which = blockIdx.x >> 3;
    int bn = blockIdx.x & 7;
    const float* W = g_w + (size_t)which * DM * DM;
    const float* b = (which == 0) ? bq : (which == 1) ? bk : bv;
    float* C = (which == 0) ? g_q : (which == 1) ? g_k : g_v;
    gemm_body<true>(g_xr, W, b, C, bn, blockIdx.y);
}

__global__ __launch_bounds__(256) void out_gemm(
    const float* __restrict__ bo, float* __restrict__ out)
{
    gemm_body<false>(g_ctx, g_w + (size_t)3 * DM * DM, bo, out, blockIdx.x, blockIdx.y);
}

// ---------------- attention: one CTA per (b,h) ----------------
__device__ __forceinline__ float bias_at(int i, int j, const float* sBias) {
    int dr = (i >> 3) - (j >> 3) + 7;
    int df = (i & 7) - (j & 7) + 7;
    return sBias[dr * 15 + df];
}

__global__ __launch_bounds__(128) void attn_kernel(const float* __restrict__ bias_table)
{
    __shared__ __align__(16) float sQ[64 * 68];
    __shared__ __align__(16) float sK[64 * 68];
    __shared__ float sBias[232];

    const int tid  = threadIdx.x;
    const int lane = tid & 31;
    const int warp = tid >> 5;
    const int g = lane >> 2, t = lane & 3;
    const int b = blockIdx.x >> 4, h = blockIdx.x & 15;

    const float* qb = g_q + (size_t)b * SEQ * DM + h * DK;
    const float* kb = g_k + (size_t)b * SEQ * DM + h * DK;
    const float* vb = g_v + (size_t)b * SEQ * DM + h * DK;

    for (int i = tid; i < 1024; i += 128) {
        int s = i >> 4, d4 = (i & 15) * 4;
        float4 qv = *(const float4*)(qb + (size_t)s * DM + d4);
        float4 kv = *(const float4*)(kb + (size_t)s * DM + d4);
        *(float4*)&sQ[s * 68 + d4] = qv;
        *(float4*)&sK[s * 68 + d4] = kv;
    }
    for (int i = tid; i < 225; i += 128) sBias[i] = bias_table[i * 16 + h];
    __syncthreads();

    // scores = Q @ K^T (Q,K already tf32 bits -> raw LDS, no CVT)
    const uint32_t* uQ = (const uint32_t*)sQ;
    const uint32_t* uK = (const uint32_t*)sK;
    float acc[8][4];
#pragma unroll
    for (int nt = 0; nt < 8; nt++)
#pragma unroll
        for (int r = 0; r < 4; r++) acc[nt][r] = 0.f;

#pragma unroll
    for (int ks = 0; ks < 8; ks++) {
        uint32_t af[4];
        int r0 = warp * 16 + g, c0 = ks * 8 + t;
        af[0] = uQ[r0 * 68 + c0];
        af[1] = uQ[(r0 + 8) * 68 + c0];
        af[2] = uQ[r0 * 68 + c0 + 4];
        af[3] = uQ[(r0 + 8) * 68 + c0 + 4];
#pragma unroll
        for (int nt = 0; nt < 8; nt++) {
            uint32_t bf[2];
            int j0 = nt * 8 + g;
            bf[0] = uK[j0 * 68 + c0];
            bf[1] = uK[j0 * 68 + c0 + 4];
            mma_tf32(acc[nt], af, bf);
        }
    }
    __syncthreads();

    const float scale = 0.125f;
#pragma unroll
    for (int nt = 0; nt < 8; nt++) {
        int i0 = warp * 16 + g, j0 = nt * 8 + t * 2;
        sQ[i0 * 68 + j0]           = acc[nt][0] * scale + bias_at(i0, j0, sBias);
        sQ[i0 * 68 + j0 + 1]       = acc[nt][1] * scale + bias_at(i0, j0 + 1, sBias);
        sQ[(i0 + 8) * 68 + j0]     = acc[nt][2] * scale + bias_at(i0 + 8, j0, sBias);
        sQ[(i0 + 8) * 68 + j0 + 1] = acc[nt][3] * scale + bias_at(i0 + 8, j0 + 1, sBias);
    }
    for (int i = tid; i < 1024; i += 128) {
        int s = i >> 4, d4 = (i & 15) * 4;
        float4 vv = *(const float4*)(vb + (size_t)s * DM + d4);
        sK[(d4 + 0) * 68 + s] = vv.x;     // V^T [d][s], already tf32 bits
        sK[(d4 + 1) * 68 + s] = vv.y;
        sK[(d4 + 2) * 68 + s] = vv.z;
        sK[(d4 + 3) * 68 + s] = vv.w;
    }
    __syncthreads();

    // softmax: 2 threads per row
    {
        int row = tid >> 1;
        float* sr = sQ + row * 68 + (tid & 1) * 32;
        float m = -1e30f;
#pragma unroll
        for (int c = 0; c < 32; c++) m = fmaxf(m, sr[c]);
        m = fmaxf(m, __shfl_xor_sync(0xffffffffu, m, 1));
        float ssum = 0.f;
#pragma unroll
        for (int c = 0; c < 32; c++) { float e = __expf(sr[c] - m); sr[c] = e; ssum += e; }
        ssum += __shfl_xor_sync(0xffffffffu, ssum, 1);
        float inv = 1.f / ssum;
#pragma unroll
        for (int c = 0; c < 32; c++) sr[c] *= inv;
    }
    __syncthreads();

    // ctx = P @ V : P needs tf32 rounding (CVT), V is raw bits
    float o[8][4];
#pragma unroll
    for (int nt = 0; nt < 8; nt++)
#pragma unroll
        for (int r = 0; r < 4; r++) o[nt][r] = 0.f;

#pragma unroll
    for (int ks = 0; ks < 8; ks++) {
        uint32_t af[4];
        int r0 = warp * 16 + g, c0 = ks * 8 + t;
        af[0] = f2tf(sQ[r0 * 68 + c0]);
        af[1] = f2tf(sQ[(r0 + 8) * 68 + c0]);
        af[2] = f2tf(sQ[r0 * 68 + c0 + 4]);
        af[3] = f2tf(sQ[(r0 + 8) * 68 + c0 + 4]);
#pragma unroll
        for (int nt = 0; nt < 8; nt++) {
            uint32_t bf[2];
            int d0 = nt * 8 + g;
            bf[0] = uK[d0 * 68 + c0];
            bf[1] = uK[d0 * 68 + c0 + 4];
            mma_tf32(o[nt], af, bf);
        }
    }

    // store ctx tf32-rounded so out_gemm needs no CVT
    float* cb = g_ctx + (size_t)b * SEQ * DM + h * DK;
#pragma unroll
    for (int nt = 0; nt < 8; nt++) {
        int i0 = warp * 16 + g, d0 = nt * 8 + t * 2;
        cb[(size_t)i0 * DM + d0]           = rnd(o[nt][0]);
        cb[(size_t)i0 * DM + d0 + 1]       = rnd(o[nt][1]);
        cb[(size_t)(i0 + 8) * DM + d0]     = rnd(o[nt][2]);
        cb[(size_t)(i0 + 8) * DM + d0 + 1] = rnd(o[nt][3]);
    }
}

// ---------------- launch ----------------
extern "C" void kernel_launch(void* const* d_in, const int* in_sizes, int n_in,
                              void* d_out, int out_size)
{
    const float* x  = (const float*)d_in[0];
    const float* Wq = (const float*)d_in[1];
    const float* bq = (const float*)d_in[2];
    const float* Wk = (const float*)d_in[3];
    const float* bk = (const float*)d_in[4];
    const float* Wv = (const float*)d_in[5];
    const float* bv = (const float*)d_in[6];
    const float* Wo = (const float*)d_in[7];
    const float* bo = (const float*)d_in[8];
    const float* bt = (const float*)d_in[9];
    float* out = (float*)d_out;

    round_x<<<16384, 256>>>(x);
    round_w<<<4096, 256>>>(Wq, Wk, Wv, Wo);
    qkv_gemm<<<dim3(24, 512), 256>>>(bq, bk, bv);
    attn_kernel<<<16384, 128>>>(bt);
    out_gemm<<<dim3(8, 512), 256>>>(bo, out);
}

// round 8
// speedup vs baseline: 1.7563x; 1.6386x over previous
#include <cuda_runtime.h>
#include <cuda_fp16.h>
#include <cstdint>
#include <cstddef>

// ---------------------------------------------------------------------------
// MHSA B=1024 S=64 D=1024 H=16 dk=64.
// R8: full fp16 datapath (m16n8k16 HMMA, fp32 accum). fp16 has the same
// 11-bit significand as tf32 -> same rounding error, 2x tensor throughput,
// half the LDS/global traffic. All operands converted at producers.
// ---------------------------------------------------------------------------

#define M_TOT   65536
#define DM      1024
#define SEQ     64
#define DK      64

__device__ __half g_xh[(size_t)M_TOT * DM];       // fp16 X
__device__ __half g_wh[(size_t)4 * DM * DM];      // fp16 W^T: [mat][n][k]
__device__ __half g_qh[(size_t)M_TOT * DM];
__device__ __half g_kh[(size_t)M_TOT * DM];
__device__ __half g_vh[(size_t)M_TOT * DM];
__device__ __half g_ch[(size_t)M_TOT * DM];       // fp16 ctx

// ---------------- PTX helpers ----------------
__device__ __forceinline__ void mma_f16(float* d, const uint32_t* a, const uint32_t* b) {
    asm volatile(
        "mma.sync.aligned.m16n8k16.row.col.f32.f16.f16.f32 "
        "{%0,%1,%2,%3}, {%4,%5,%6,%7}, {%8,%9}, {%0,%1,%2,%3};"
        : "+f"(d[0]), "+f"(d[1]), "+f"(d[2]), "+f"(d[3])
        : "r"(a[0]), "r"(a[1]), "r"(a[2]), "r"(a[3]), "r"(b[0]), "r"(b[1]));
}
__device__ __forceinline__ void cp16(uint32_t s, const void* g) {
    asm volatile("cp.async.ca.shared.global [%0], [%1], 16;" :: "r"(s), "l"(g));
}
__device__ __forceinline__ void cp_commit() { asm volatile("cp.async.commit_group;"); }
__device__ __forceinline__ void cp_wait0()  { asm volatile("cp.async.wait_group 0;"); }

// ---------------- prepasses ----------------
__global__ __launch_bounds__(256) void half_x(const float* __restrict__ x) {
    const float4* src = (const float4*)x;
    uint2* dst = (uint2*)g_xh;
#pragma unroll
    for (int j = 0; j < 4; j++) {
        size_t i = (size_t)blockIdx.x * 1024 + j * 256 + threadIdx.x;
        float4 v = src[i];
        __half2 lo = __floats2half2_rn(v.x, v.y);
        __half2 hi = __floats2half2_rn(v.z, v.w);
        uint2 o;
        o.x = *(uint32_t*)&lo;
        o.y = *(uint32_t*)&hi;
        dst[i] = o;
    }
}

// W[k][n] fp32 -> W^T[n][k] fp16
__global__ void half_wT(const float* __restrict__ Wq, const float* __restrict__ Wk,
                        const float* __restrict__ Wv, const float* __restrict__ Wo)
{
    __shared__ __half t[32][33];
    const int z = blockIdx.z;
    const float* src = (z == 0) ? Wq : (z == 1) ? Wk : (z == 2) ? Wv : Wo;
    __half* dst = g_wh + (size_t)z * DM * DM;
    const int tx = threadIdx.x, ty = threadIdx.y;
    const int bx = blockIdx.x * 32, by = blockIdx.y * 32;
#pragma unroll
    for (int j = 0; j < 4; j++)
        t[ty + 8 * j][tx] = __float2half(src[(size_t)(by + ty + 8 * j) * DM + bx + tx]);
    __syncthreads();
#pragma unroll
    for (int j = 0; j < 4; j++)
        dst[(size_t)(bx + ty + 8 * j) * DM + by + tx] = t[tx][ty + 8 * j];
}

// ---------------- GEMM: C[128x128] = A[.,1024] @ W^T[n][k] + bias ----------
// BM=128 BN=128 BK=32, 256 thr = 8 warps (2m x 4n), warp tile 64x32.
// smem stride 40 halves (20 uints): frag banks (20g+t)%32 all distinct.
#define GST 20   // uint stride

template <bool HALF_OUT>
__device__ __forceinline__ void gemm_body(
    const __half* __restrict__ A, const __half* __restrict__ Bt,
    const float* __restrict__ bias, void* __restrict__ Cout,
    int bn, int bm)
{
    __shared__ __align__(16) __half sA[2][128 * 40];
    __shared__ __align__(16) __half sB[2][128 * 40];

    const int tid  = threadIdx.x;
    const int lane = tid & 31;
    const int warp = tid >> 5;
    const int wm = warp >> 2, wn = warp & 3;
    const int g  = lane >> 2, t = lane & 3;

    const __half* Ab = A + (size_t)bm * 128 * DM;
    const __half* Bb = Bt + (size_t)bn * 128 * DM;

    float acc[4][4][4];
#pragma unroll
    for (int i = 0; i < 4; i++)
#pragma unroll
        for (int j = 0; j < 4; j++)
#pragma unroll
            for (int r = 0; r < 4; r++) acc[i][j][r] = 0.f;

    auto load_chunk = [&](int kc, int buf) {
#pragma unroll
        for (int c = 0; c < 2; c++) {
            int id = tid + c * 256;          // 0..511
            int row = id >> 2, c16 = (id & 3) * 8;   // 8 halves per 16B
            cp16((uint32_t)__cvta_generic_to_shared(&sA[buf][row * 40 + c16]),
                 Ab + (size_t)row * DM + kc * 32 + c16);
            cp16((uint32_t)__cvta_generic_to_shared(&sB[buf][row * 40 + c16]),
                 Bb + (size_t)row * DM + kc * 32 + c16);
        }
        cp_commit();
    };

    load_chunk(0, 0);
#pragma unroll 1
    for (int kc = 0; kc < 32; kc++) {
        cp_wait0();
        __syncthreads();
        if (kc < 31) load_chunk(kc + 1, (kc + 1) & 1);
        const uint32_t* cA = (const uint32_t*)sA[kc & 1];
        const uint32_t* cB = (const uint32_t*)sB[kc & 1];
#pragma unroll
        for (int ks = 0; ks < 2; ks++) {
            const int k2 = ks * 8 + t;
            uint32_t af[4][4];
#pragma unroll
            for (int mt = 0; mt < 4; mt++) {
                int R = wm * 64 + mt * 16 + g;
                af[mt][0] = cA[R * GST + k2];
                af[mt][1] = cA[(R + 8) * GST + k2];
                af[mt][2] = cA[R * GST + k2 + 4];
                af[mt][3] = cA[(R + 8) * GST + k2 + 4];
            }
            uint32_t bf[4][2];
#pragma unroll
            for (int nt = 0; nt < 4; nt++) {
                int N = wn * 32 + nt * 8 + g;
                bf[nt][0] = cB[N * GST + k2];
                bf[nt][1] = cB[N * GST + k2 + 4];
            }
#pragma unroll
            for (int mt = 0; mt < 4; mt++)
#pragma unroll
                for (int nt = 0; nt < 4; nt++)
                    mma_f16(acc[mt][nt], af[mt], bf[nt]);
        }
        __syncthreads();
    }

#pragma unroll
    for (int mt = 0; mt < 4; mt++) {
        int r0 = bm * 128 + wm * 64 + mt * 16 + g;
#pragma unroll
        for (int nt = 0; nt < 4; nt++) {
            int c0 = bn * 128 + wn * 32 + nt * 8 + t * 2;
            float b0 = bias[c0], b1 = bias[c0 + 1];
            float v0 = acc[mt][nt][0] + b0;
            float v1 = acc[mt][nt][1] + b1;
            float v2 = acc[mt][nt][2] + b0;
            float v3 = acc[mt][nt][3] + b1;
            if (HALF_OUT) {
                __half* C = (__half*)Cout;
                *(__half2*)(C + (size_t)r0 * DM + c0)       = __floats2half2_rn(v0, v1);
                *(__half2*)(C + (size_t)(r0 + 8) * DM + c0) = __floats2half2_rn(v2, v3);
            } else {
                float* C = (float*)Cout;
                C[(size_t)r0 * DM + c0]           = v0;
                C[(size_t)r0 * DM + c0 + 1]       = v1;
                C[(size_t)(r0 + 8) * DM + c0]     = v2;
                C[(size_t)(r0 + 8) * DM + c0 + 1] = v3;
            }
        }
    }
}

__global__ __launch_bounds__(256) void qkv_gemm(
    const float* __restrict__ bq, const float* __restrict__ bk, const float* __restrict__ bv)
{
    int which = blockIdx.x >> 3;
    int bn = blockIdx.x & 7;
    const __half* W = g_wh + (size_t)which * DM * DM;
    const float* b = (which == 0) ? bq : (which == 1) ? bk : bv;
    __half* C = (which == 0) ? g_qh : (which == 1) ? g_kh : g_vh;
    gemm_body<true>(g_xh, W, b, C, bn, blockIdx.y);
}

__global__ __launch_bounds__(256) void out_gemm(
    const float* __restrict__ bo, float* __restrict__ out)
{
    gemm_body<false>(g_ch, g_wh + (size_t)3 * DM * DM, bo, out, blockIdx.x, blockIdx.y);
}

// ---------------- attention: one CTA (128 thr) per (b,h) ----------------
// smem half buffers stride 72 halves (36 uints): frag banks (4g+t)%32 distinct.
// Phase A: sQ=Q, sK=K -> scores. Phase B: sQ=V^T, sK=P.
__device__ __forceinline__ float bias_at(int i, int j, const float* sBias) {
    int dr = (i >> 3) - (j >> 3) + 7;
    int df = (i & 7) - (j & 7) + 7;
    return sBias[dr * 15 + df];
}

__global__ __launch_bounds__(128) void attn_kernel(const float* __restrict__ bias_table)
{
    __shared__ __align__(16) __half sQ[64 * 72];   // Q, then V^T [d][s]
    __shared__ __align__(16) __half sK[64 * 72];   // K, then P
    __shared__ __align__(16) float  sS[64 * 68];   // fp32 scores
    __shared__ float sBias[232];

    const int tid  = threadIdx.x;
    const int lane = tid & 31;
    const int warp = tid >> 5;
    const int g = lane >> 2, t = lane & 3;
    const int b = blockIdx.x >> 4, h = blockIdx.x & 15;

    const __half* qb = g_qh + (size_t)b * SEQ * DM + h * DK;
    const __half* kb = g_kh + (size_t)b * SEQ * DM + h * DK;
    const __half* vb = g_vh + (size_t)b * SEQ * DM + h * DK;

    // load Q, K: 64 rows x 64 halves (128B) as uint4
    for (int i = tid; i < 512; i += 128) {
        int s = i >> 3, c = i & 7;
        uint4 qv = ((const uint4*)(qb + (size_t)s * DM))[c];
        uint4 kv = ((const uint4*)(kb + (size_t)s * DM))[c];
        ((uint4*)(sQ + s * 72))[c] = qv;
        ((uint4*)(sK + s * 72))[c] = kv;
    }
    for (int i = tid; i < 225; i += 128) sBias[i] = bias_table[i * 16 + h];
    __syncthreads();

    const uint32_t* uQ = (const uint32_t*)sQ;
    const uint32_t* uK = (const uint32_t*)sK;

    // scores = Q @ K^T, m16n8k16, 4 k-steps
    float acc[8][4];
#pragma unroll
    for (int nt = 0; nt < 8; nt++)
#pragma unroll
        for (int r = 0; r < 4; r++) acc[nt][r] = 0.f;

#pragma unroll
    for (int ks = 0; ks < 4; ks++) {
        const int k2 = ks * 8 + t;
        uint32_t af[4];
        int R = warp * 16 + g;
        af[0] = uQ[R * 36 + k2];
        af[1] = uQ[(R + 8) * 36 + k2];
        af[2] = uQ[R * 36 + k2 + 4];
        af[3] = uQ[(R + 8) * 36 + k2 + 4];
#pragma unroll
        for (int nt = 0; nt < 8; nt++) {
            int J = nt * 8 + g;
            uint32_t bf[2];
            bf[0] = uK[J * 36 + k2];
            bf[1] = uK[J * 36 + k2 + 4];
            mma_f16(acc[nt], af, bf);
        }
    }
    __syncthreads();   // Q/K reads done; buffers reusable

    // scores -> sS (scaled + bias); V^T -> sQ
    const float scale = 0.125f;
#pragma unroll
    for (int nt = 0; nt < 8; nt++) {
        int i0 = warp * 16 + g, j0 = nt * 8 + t * 2;
        sS[i0 * 68 + j0]           = acc[nt][0] * scale + bias_at(i0, j0, sBias);
        sS[i0 * 68 + j0 + 1]       = acc[nt][1] * scale + bias_at(i0, j0 + 1, sBias);
        sS[(i0 + 8) * 68 + j0]     = acc[nt][2] * scale + bias_at(i0 + 8, j0, sBias);
        sS[(i0 + 8) * 68 + j0 + 1] = acc[nt][3] * scale + bias_at(i0 + 8, j0 + 1, sBias);
    }
    for (int i = tid; i < 2048; i += 128) {      // V [s][d] -> V^T [d][s]
        int s = i >> 5, dp = i & 31;
        uint32_t v = ((const uint32_t*)(vb + (size_t)s * DM))[dp];
        __half2 h2 = *(__half2*)&v;
        sQ[(2 * dp) * 72 + s]     = __low2half(h2);
        sQ[(2 * dp + 1) * 72 + s] = __high2half(h2);
    }
    __syncthreads();

    // softmax (2 threads/row); write P as fp16 into sK
    {
        int row = tid >> 1;
        float* sr = sS + row * 68 + (tid & 1) * 32;
        __half* pr = sK + row * 72 + (tid & 1) * 32;
        float m = -1e30f;
#pragma unroll
        for (int c = 0; c < 32; c++) m = fmaxf(m, sr[c]);
        m = fmaxf(m, __shfl_xor_sync(0xffffffffu, m, 1));
        float e[32], ssum = 0.f;
#pragma unroll
        for (int c = 0; c < 32; c++) { e[c] = __expf(sr[c] - m); ssum += e[c]; }
        ssum += __shfl_xor_sync(0xffffffffu, ssum, 1);
        float inv = 1.f / ssum;
#pragma unroll
        for (int c = 0; c < 32; c++) pr[c] = __float2half(e[c] * inv);
    }
    __syncthreads();

    // ctx = P @ V : A=P (sK), B=V^T (sQ)
    float o[8][4];
#pragma unroll
    for (int nt = 0; nt < 8; nt++)
#pragma unroll
        for (int r = 0; r < 4; r++) o[nt][r] = 0.f;

#pragma unroll
    for (int ks = 0; ks < 4; ks++) {
        const int k2 = ks * 8 + t;
        uint32_t af[4];
        int R = warp * 16 + g;
        af[0] = uK[R * 36 + k2];
        af[1] = uK[(R + 8) * 36 + k2];
        af[2] = uK[R * 36 + k2 + 4];
        af[3] = uK[(R + 8) * 36 + k2 + 4];
#pragma unroll
        for (int nt = 0; nt < 8; nt++) {
            int D = nt * 8 + g;
            uint32_t bf[2];
            bf[0] = uQ[D * 36 + k2];
            bf[1] = uQ[D * 36 + k2 + 4];
            mma_f16(o[nt], af, bf);
        }
    }

    __half* cb = g_ch + (size_t)b * SEQ * DM + h * DK;
#pragma unroll
    for (int nt = 0; nt < 8; nt++) {
        int i0 = warp * 16 + g, d0 = nt * 8 + t * 2;
        *(__half2*)(cb + (size_t)i0 * DM + d0)       = __floats2half2_rn(o[nt][0], o[nt][1]);
        *(__half2*)(cb + (size_t)(i0 + 8) * DM + d0) = __floats2half2_rn(o[nt][2], o[nt][3]);
    }
}

// ---------------- launch ----------------
extern "C" void kernel_launch(void* const* d_in, const int* in_sizes, int n_in,
                              void* d_out, int out_size)
{
    const float* x  = (const float*)d_in[0];
    const float* Wq = (const float*)d_in[1];
    const float* bq = (const float*)d_in[2];
    const float* Wk = (const float*)d_in[3];
    const float* bk = (const float*)d_in[4];
    const float* Wv = (const float*)d_in[5];
    const float* bv = (const float*)d_in[6];
    const float* Wo = (const float*)d_in[7];
    const float* bo = (const float*)d_in[8];
    const float* bt = (const float*)d_in[9];
    float* out = (float*)d_out;

    half_x<<<16384, 256>>>(x);
    half_wT<<<dim3(32, 32, 4), dim3(32, 8)>>>(Wq, Wk, Wv, Wo);
    qkv_gemm<<<dim3(24, 512), 256>>>(bq, bk, bv);
    attn_kernel<<<16384, 128>>>(bt);
    out_gemm<<<dim3(8, 512), 256>>>(bo, out);
}

// round 9
// speedup vs baseline: 2.5624x; 1.4590x over previous
#include <cuda_runtime.h>
#include <cuda_fp16.h>
#include <cstdint>
#include <cstddef>

// ---------------------------------------------------------------------------
// MHSA B=1024 S=64 D=1024 H=16 dk=64.
// R9: fp16 m16n8k16 HMMA. GEMM: 64x64 warp tiles + ldmatrix (crossbar-traffic
// fix). Attention: register-resident softmax (P never hits smem), V via
// ldmatrix.trans, single __syncthreads.
// ---------------------------------------------------------------------------

#define M_TOT   65536
#define DM      1024
#define SEQ     64
#define DK      64

__device__ __half g_xh[(size_t)M_TOT * DM];
__device__ __half g_wh[(size_t)4 * DM * DM];      // fp16 W^T: [mat][n][k]
__device__ __half g_qh[(size_t)M_TOT * DM];
__device__ __half g_kh[(size_t)M_TOT * DM];
__device__ __half g_vh[(size_t)M_TOT * DM];
__device__ __half g_ch[(size_t)M_TOT * DM];

// ---------------- PTX helpers ----------------
__device__ __forceinline__ void mma_f16(float* d, const uint32_t* a, const uint32_t* b) {
    asm volatile(
        "mma.sync.aligned.m16n8k16.row.col.f32.f16.f16.f32 "
        "{%0,%1,%2,%3}, {%4,%5,%6,%7}, {%8,%9}, {%0,%1,%2,%3};"
        : "+f"(d[0]), "+f"(d[1]), "+f"(d[2]), "+f"(d[3])
        : "r"(a[0]), "r"(a[1]), "r"(a[2]), "r"(a[3]), "r"(b[0]), "r"(b[1]));
}
__device__ __forceinline__ void ldsm4(uint32_t* r, uint32_t a) {
    asm volatile("ldmatrix.sync.aligned.m8n8.x4.shared.b16 {%0,%1,%2,%3}, [%4];"
                 : "=r"(r[0]), "=r"(r[1]), "=r"(r[2]), "=r"(r[3]) : "r"(a));
}
__device__ __forceinline__ void ldsm4t(uint32_t* r, uint32_t a) {
    asm volatile("ldmatrix.sync.aligned.m8n8.x4.trans.shared.b16 {%0,%1,%2,%3}, [%4];"
                 : "=r"(r[0]), "=r"(r[1]), "=r"(r[2]), "=r"(r[3]) : "r"(a));
}
__device__ __forceinline__ void cp16(uint32_t s, const void* g) {
    asm volatile("cp.async.ca.shared.global [%0], [%1], 16;" :: "r"(s), "l"(g));
}
__device__ __forceinline__ void cp_commit() { asm volatile("cp.async.commit_group;"); }
__device__ __forceinline__ void cp_wait0()  { asm volatile("cp.async.wait_group 0;"); }
__device__ __forceinline__ uint32_t scvt(const void* p) {
    return (uint32_t)__cvta_generic_to_shared(p);
}

// ---------------- prepasses ----------------
__global__ __launch_bounds__(256) void half_x(const float* __restrict__ x) {
    const float4* src = (const float4*)x;
    uint2* dst = (uint2*)g_xh;
#pragma unroll
    for (int j = 0; j < 4; j++) {
        size_t i = (size_t)blockIdx.x * 1024 + j * 256 + threadIdx.x;
        float4 v = src[i];
        __half2 lo = __floats2half2_rn(v.x, v.y);
        __half2 hi = __floats2half2_rn(v.z, v.w);
        uint2 o;
        o.x = *(uint32_t*)&lo;
        o.y = *(uint32_t*)&hi;
        dst[i] = o;
    }
}

__global__ void half_wT(const float* __restrict__ Wq, const float* __restrict__ Wk,
                        const float* __restrict__ Wv, const float* __restrict__ Wo)
{
    __shared__ __half t[32][33];
    const int z = blockIdx.z;
    const float* src = (z == 0) ? Wq : (z == 1) ? Wk : (z == 2) ? Wv : Wo;
    __half* dst = g_wh + (size_t)z * DM * DM;
    const int tx = threadIdx.x, ty = threadIdx.y;
    const int bx = blockIdx.x * 32, by = blockIdx.y * 32;
#pragma unroll
    for (int j = 0; j < 4; j++)
        t[ty + 8 * j][tx] = __float2half(src[(size_t)(by + ty + 8 * j) * DM + bx + tx]);
    __syncthreads();
#pragma unroll
    for (int j = 0; j < 4; j++)
        dst[(size_t)(bx + ty + 8 * j) * DM + by + tx] = t[tx][ty + 8 * j];
}

// ---------------- GEMM: C[128x128] = A[.,1024] @ W^T[n][k] + bias ----------
// 128 threads = 4 warps (2m x 2n), warp tile 64x64, BK=32.
// smem stride 40 halves (80B = 5 quads): LDSM 8-lane groups conflict-free.
#define GST 40   // half stride

template <bool HALF_OUT>
__device__ __forceinline__ void gemm_body(
    const __half* __restrict__ A, const __half* __restrict__ Bt,
    const float* __restrict__ bias, void* __restrict__ Cout,
    int bn, int bm)
{
    __shared__ __align__(16) __half sA[2][128 * GST];
    __shared__ __align__(16) __half sB[2][128 * GST];

    const int tid  = threadIdx.x;
    const int lane = tid & 31;
    const int warp = tid >> 5;
    const int wm = warp >> 1, wn = warp & 1;
    const int g  = lane >> 2, t = lane & 3;

    const __half* Ab = A + (size_t)bm * 128 * DM;
    const __half* Bb = Bt + (size_t)bn * 128 * DM;

    float acc[4][8][4];
#pragma unroll
    for (int i = 0; i < 4; i++)
#pragma unroll
        for (int j = 0; j < 8; j++)
#pragma unroll
            for (int r = 0; r < 4; r++) acc[i][j][r] = 0.f;

    const uint32_t sAu = scvt(sA);
    const uint32_t sBu = scvt(sB);

    // per-thread LDSM address invariants
    const uint32_t aBase = sAu + (uint32_t)(((wm * 64 + (lane & 15)) * GST + (lane >> 4) * 8) * 2);
    const int bmi = lane >> 3, br8 = lane & 7;
    const uint32_t bBase = sBu + (uint32_t)(((wn * 64 + (bmi >> 1) * 8 + br8) * GST + (bmi & 1) * 8) * 2);

    auto load_chunk = [&](int kc, int buf) {
        const uint32_t aS = sAu + buf * (128 * GST * 2);
        const uint32_t bS = sBu + buf * (128 * GST * 2);
#pragma unroll
        for (int c = 0; c < 4; c++) {
            int id = tid + c * 128;                 // 0..511
            int row = id >> 2, c8 = (id & 3) * 8;   // 8 halves per 16B
            cp16(aS + (uint32_t)((row * GST + c8) * 2), Ab + (size_t)row * DM + kc * 32 + c8);
            cp16(bS + (uint32_t)((row * GST + c8) * 2), Bb + (size_t)row * DM + kc * 32 + c8);
        }
        cp_commit();
    };

    load_chunk(0, 0);
#pragma unroll 1
    for (int kc = 0; kc < 32; kc++) {
        cp_wait0();
        __syncthreads();
        if (kc < 31) load_chunk(kc + 1, (kc + 1) & 1);
        const uint32_t bufO = (kc & 1) * (128 * GST * 2);
#pragma unroll
        for (int ks = 0; ks < 2; ks++) {
            uint32_t af[4][4];
#pragma unroll
            for (int mt = 0; mt < 4; mt++)
                ldsm4(af[mt], aBase + bufO + mt * (16 * GST * 2) + ks * 32);
            uint32_t bf[4][4];
#pragma unroll
            for (int j = 0; j < 4; j++)
                ldsm4(bf[j], bBase + bufO + j * (16 * GST * 2) + ks * 32);
#pragma unroll
            for (int mt = 0; mt < 4; mt++)
#pragma unroll
                for (int nt = 0; nt < 8; nt++)
                    mma_f16(acc[mt][nt], af[mt], bf[nt >> 1] + (nt & 1) * 2);
        }
        __syncthreads();
    }

#pragma unroll
    for (int mt = 0; mt < 4; mt++) {
        int r0 = bm * 128 + wm * 64 + mt * 16 + g;
#pragma unroll
        for (int nt = 0; nt < 8; nt++) {
            int c0 = bn * 128 + wn * 64 + nt * 8 + t * 2;
            float b0 = bias[c0], b1 = bias[c0 + 1];
            float v0 = acc[mt][nt][0] + b0;
            float v1 = acc[mt][nt][1] + b1;
            float v2 = acc[mt][nt][2] + b0;
            float v3 = acc[mt][nt][3] + b1;
            if (HALF_OUT) {
                __half* C = (__half*)Cout;
                *(__half2*)(C + (size_t)r0 * DM + c0)       = __floats2half2_rn(v0, v1);
                *(__half2*)(C + (size_t)(r0 + 8) * DM + c0) = __floats2half2_rn(v2, v3);
            } else {
                float* C = (float*)Cout;
                C[(size_t)r0 * DM + c0]           = v0;
                C[(size_t)r0 * DM + c0 + 1]       = v1;
                C[(size_t)(r0 + 8) * DM + c0]     = v2;
                C[(size_t)(r0 + 8) * DM + c0 + 1] = v3;
            }
        }
    }
}

__global__ __launch_bounds__(128) void qkv_gemm(
    const float* __restrict__ bq, const float* __restrict__ bk, const float* __restrict__ bv)
{
    int which = blockIdx.x >> 3;
    int bn = blockIdx.x & 7;
    const __half* W = g_wh + (size_t)which * DM * DM;
    const float* b = (which == 0) ? bq : (which == 1) ? bk : bv;
    __half* C = (which == 0) ? g_qh : (which == 1) ? g_kh : g_vh;
    gemm_body<true>(g_xh, W, b, C, bn, blockIdx.y);
}

__global__ __launch_bounds__(128) void out_gemm(
    const float* __restrict__ bo, float* __restrict__ out)
{
    gemm_body<false>(g_ch, g_wh + (size_t)3 * DM * DM, bo, out, blockIdx.x, blockIdx.y);
}

// ---------------- attention: one CTA (128 thr) per (b,h) ----------------
// Q,K,V in smem (stride 72 halves = 9 quads: LDSM conflict-free).
// scores -> registers; softmax in registers (4-lane shuffles); P stays in
// registers as the next A-fragment; V consumed via ldmatrix.x4.trans.
__device__ __forceinline__ float bias_at(int i, int j, const float* sBias) {
    int dr = (i >> 3) - (j >> 3) + 7;
    int df = (i & 7) - (j & 7) + 7;
    return sBias[dr * 15 + df];
}

#define AST 72   // half stride

__global__ __launch_bounds__(128, 5) void attn_kernel(const float* __restrict__ bias_table)
{
    __shared__ __align__(16) __half sQ[64 * AST];
    __shared__ __align__(16) __half sK[64 * AST];
    __shared__ __align__(16) __half sV[64 * AST];
    __shared__ float sBias[232];

    const int tid  = threadIdx.x;
    const int lane = tid & 31;
    const int warp = tid >> 5;
    const int g = lane >> 2, t = lane & 3;
    const int b = blockIdx.x >> 4, h = blockIdx.x & 15;

    const __half* qb = g_qh + (size_t)b * SEQ * DM + h * DK;
    const __half* kb = g_kh + (size_t)b * SEQ * DM + h * DK;
    const __half* vb = g_vh + (size_t)b * SEQ * DM + h * DK;

    // load Q, K, V (each 64 rows x 128B)
    for (int i = tid; i < 512; i += 128) {
        int s = i >> 3, c = i & 7;
        uint4 qv = ((const uint4*)(qb + (size_t)s * DM))[c];
        uint4 kv = ((const uint4*)(kb + (size_t)s * DM))[c];
        uint4 vv = ((const uint4*)(vb + (size_t)s * DM))[c];
        ((uint4*)(sQ + s * AST))[c] = qv;
        ((uint4*)(sK + s * AST))[c] = kv;
        ((uint4*)(sV + s * AST))[c] = vv;
    }
    for (int i = tid; i < 225; i += 128) sBias[i] = bias_table[i * 16 + h];
    __syncthreads();   // the ONLY barrier

    const uint32_t sQu = scvt(sQ), sKu = scvt(sK), sVu = scvt(sV);

    // ---- scores = Q @ K^T : rows warp*16+{g,g+8}, all 64 cols ----
    const uint32_t qBase = sQu + (uint32_t)(((warp * 16 + (lane & 15)) * AST + (lane >> 4) * 8) * 2);
    const int bmi = lane >> 3, br8 = lane & 7;
    const uint32_t kBase = sKu + (uint32_t)((((bmi >> 1) * 8 + br8) * AST + (bmi & 1) * 8) * 2);

    float acc[8][4];
#pragma unroll
    for (int nt = 0; nt < 8; nt++)
#pragma unroll
        for (int r = 0; r < 4; r++) acc[nt][r] = 0.f;

#pragma unroll
    for (int ks = 0; ks < 4; ks++) {
        uint32_t af[4];
        ldsm4(af, qBase + ks * 32);
#pragma unroll
        for (int j = 0; j < 4; j++) {
            uint32_t bf[4];
            ldsm4(bf, kBase + j * (16 * AST * 2) + ks * 32);
            mma_f16(acc[2 * j],     af, bf);
            mma_f16(acc[2 * j + 1], af, bf + 2);
        }
    }

    // ---- scale + bias + softmax, entirely in registers ----
    const float scale = 0.125f;
    const int i0 = warp * 16 + g;
    float mlo = -1e30f, mhi = -1e30f;
#pragma unroll
    for (int nt = 0; nt < 8; nt++) {
        int j0 = nt * 8 + t * 2;
        acc[nt][0] = acc[nt][0] * scale + bias_at(i0, j0, sBias);
        acc[nt][1] = acc[nt][1] * scale + bias_at(i0, j0 + 1, sBias);
        acc[nt][2] = acc[nt][2] * scale + bias_at(i0 + 8, j0, sBias);
        acc[nt][3] = acc[nt][3] * scale + bias_at(i0 + 8, j0 + 1, sBias);
        mlo = fmaxf(mlo, fmaxf(acc[nt][0], acc[nt][1]));
        mhi = fmaxf(mhi, fmaxf(acc[nt][2], acc[nt][3]));
    }
    mlo = fmaxf(mlo, __shfl_xor_sync(0xffffffffu, mlo, 1));
    mlo = fmaxf(mlo, __shfl_xor_sync(0xffffffffu, mlo, 2));
    mhi = fmaxf(mhi, __shfl_xor_sync(0xffffffffu, mhi, 1));
    mhi = fmaxf(mhi, __shfl_xor_sync(0xffffffffu, mhi, 2));
    float slo = 0.f, shi = 0.f;
#pragma unroll
    for (int nt = 0; nt < 8; nt++) {
        acc[nt][0] = __expf(acc[nt][0] - mlo);
        acc[nt][1] = __expf(acc[nt][1] - mlo);
        acc[nt][2] = __expf(acc[nt][2] - mhi);
        acc[nt][3] = __expf(acc[nt][3] - mhi);
        slo += acc[nt][0] + acc[nt][1];
        shi += acc[nt][2] + acc[nt][3];
    }
    slo += __shfl_xor_sync(0xffffffffu, slo, 1);
    slo += __shfl_xor_sync(0xffffffffu, slo, 2);
    shi += __shfl_xor_sync(0xffffffffu, shi, 1);
    shi += __shfl_xor_sync(0xffffffffu, shi, 2);
    const float ilo = 1.f / slo, ihi = 1.f / shi;

    // pack P into A-fragments (register layout already matches!)
    uint32_t plo[8], phi[8];
#pragma unroll
    for (int nt = 0; nt < 8; nt++) {
        __half2 hl = __floats2half2_rn(acc[nt][0] * ilo, acc[nt][1] * ilo);
        __half2 hh = __floats2half2_rn(acc[nt][2] * ihi, acc[nt][3] * ihi);
        plo[nt] = *(uint32_t*)&hl;
        phi[nt] = *(uint32_t*)&hh;
    }

    // ---- ctx = P @ V : V via ldmatrix.trans from [s][d] ----
    __half* cb = g_ch + (size_t)b * SEQ * DM + h * DK;
#pragma unroll
    for (int nt = 0; nt < 8; nt++) {
        // two trans-x4 loads cover ksteps {0,1} and {2,3} for d-tile nt
        uint32_t v01[4], v23[4];
        ldsm4t(v01, sVu + (uint32_t)(((lane) * AST + nt * 8) * 2));
        ldsm4t(v23, sVu + (uint32_t)(((32 + lane) * AST + nt * 8) * 2));
        float o[4] = {0.f, 0.f, 0.f, 0.f};
#pragma unroll
        for (int ks = 0; ks < 4; ks++) {
            uint32_t af[4] = {plo[2 * ks], phi[2 * ks], plo[2 * ks + 1], phi[2 * ks + 1]};
            const uint32_t* bf = (ks < 2) ? (v01 + ks * 2) : (v23 + (ks - 2) * 2);
            mma_f16(o, af, bf);
        }
        int d0 = nt * 8 + t * 2;
        *(__half2*)(cb + (size_t)i0 * DM + d0)       = __floats2half2_rn(o[0], o[1]);
        *(__half2*)(cb + (size_t)(i0 + 8) * DM + d0) = __floats2half2_rn(o[2], o[3]);
    }
}

// ---------------- launch ----------------
extern "C" void kernel_launch(void* const* d_in, const int* in_sizes, int n_in,
                              void* d_out, int out_size)
{
    const float* x  = (const float*)d_in[0];
    const float* Wq = (const float*)d_in[1];
    const float* bq = (const float*)d_in[2];
    const float* Wk = (const float*)d_in[3];
    const float* bk = (const float*)d_in[4];
    const float* Wv = (const float*)d_in[5];
    const float* bv = (const float*)d_in[6];
    const float* Wo = (const float*)d_in[7];
    const float* bo = (const float*)d_in[8];
    const float* bt = (const float*)d_in[9];
    float* out = (float*)d_out;

    half_x<<<16384, 256>>>(x);
    half_wT<<<dim3(32, 32, 4), dim3(32, 8)>>>(Wq, Wk, Wv, Wo);
    qkv_gemm<<<dim3(24, 512), 128>>>(bq, bk, bv);
    attn_kernel<<<16384, 128>>>(bt);
    out_gemm<<<dim3(8, 512), 128>>>(bo, out);
}